// round 16
// baseline (speedup 1.0000x reference)
#include <cuda_runtime.h>
#include <math.h>

#define EMBED    2048
#define NEXP     64
#define TOPK     8
#define KC       16                 // K per chunk
#define NCHUNK   128
#define TOKS     128                // tokens per CTA
#define THREADS  128                // 4 warps; warp = 16 experts, lane = 4 tokens
#define NBLK     256
#define TP       132                // xT row stride (floats), 16B-aligned

#define W_BYTES   4096u             // 16k x 64e x 4B
#define XT_BYTES  8448u             // 16k x 132 x 4B
#define SM_W      0u
#define SM_XT     8192u             // 2 x 8448 -> GEMM region ends at 25088
#define SM_LS     0u                // alias after GEMM: 128 x 65 f32 = 33280
#define SM_CNT    33280u
#define SMEM_TOTAL 33536u

typedef unsigned long long u64;

__device__ float        g_wt[EMBED * NEXP];   // W transposed: [k][e]
__device__ float        g_pi_part[NBLK][NEXP];
__device__ unsigned int g_cnt[NEXP];

__global__ void prep_kernel(const float* __restrict__ w) {
    int idx = blockIdx.x * blockDim.x + threadIdx.x;   // e*2048 + k
    int e = idx >> 11, k = idx & 2047;
    g_wt[k * NEXP + e] = w[idx];
    if (idx < NEXP) g_cnt[idx] = 0u;
}

// Profiling alignment: 5-launch cycle [prep, dummy, dummy, gate, finalize]
// puts ncu's "-s 5 -c 1" capture on gate_kernel.
__global__ void dummy_kernel() {}

__device__ __forceinline__ u64 ffma2(u64 a, u64 b, u64 c) {
    u64 d;
    asm("fma.rn.f32x2 %0, %1, %2, %3;" : "=l"(d) : "l"(a), "l"(b), "l"(c));
    return d;
}
__device__ __forceinline__ u64 pack2(float f) {
    u64 d;
    asm("mov.b64 %0, {%1, %1};" : "=l"(d) : "f"(f));
    return d;
}
__device__ __forceinline__ void lds_v2(u64& a, u64& b, unsigned addr) {
    asm volatile("ld.shared.v2.b64 {%0, %1}, [%2];" : "=l"(a), "=l"(b) : "r"(addr));
}
__device__ __forceinline__ void cp_async16(unsigned saddr, const void* gaddr) {
    asm volatile("cp.async.ca.shared.global [%0], [%1], 16;" :: "r"(saddr), "l"(gaddr));
}
__device__ __forceinline__ void cp_commit()  { asm volatile("cp.async.commit_group;"); }
__device__ __forceinline__ void cp_wait0()   { asm volatile("cp.async.wait_group 0;" ::: "memory"); }

__global__ void __launch_bounds__(THREADS, 2) gate_kernel(
    const float* __restrict__ x, float* __restrict__ out, int ntok)
{
    extern __shared__ __align__(16) unsigned char smx[];
    const unsigned sb = (unsigned)__cvta_generic_to_shared(smx);
    const int t = threadIdx.x, lane = t & 31, wid = t >> 5;
    const long tokBase = (long)blockIdx.x * TOKS;

    if (t < NEXP) *(unsigned*)(smx + SM_CNT + 4u * t) = 0u;

    u64 acc[4][8];                    // [token tt][expert-pair p]
    #pragma unroll
    for (int tt = 0; tt < 4; tt++)
        #pragma unroll
        for (int p = 0; p < 8; p++) acc[tt][p] = 0ULL;

    // ---------------- prologue: stage chunk 0 ----------------
    float4 xv[4];
    {
        #pragma unroll
        for (int j = 0; j < 2; j++) {             // W0: 256 float4 / 128 thr
            int f = t + j * THREADS;
            cp_async16(sb + SM_W + (unsigned)f * 16u, g_wt + f * 4);
        }
        cp_commit();
        #pragma unroll
        for (int j = 0; j < 4; j++) {             // x0: 512 float4 / 128 thr
            int f = t + j * THREADS;
            int tok = f >> 2, kq = f & 3;
            xv[j] = *(const float4*)(x + (tokBase + tok) * EMBED + kq * 4);
        }
        float* xt = (float*)(smx + SM_XT);
        #pragma unroll
        for (int j = 0; j < 4; j++) {             // transpose STS
            int f = t + j * THREADS;
            int tok = f >> 2, kq = f & 3;
            xt[(kq * 4 + 0) * TP + tok] = xv[j].x;
            xt[(kq * 4 + 1) * TP + tok] = xv[j].y;
            xt[(kq * 4 + 2) * TP + tok] = xv[j].z;
            xt[(kq * 4 + 3) * TP + tok] = xv[j].w;
        }
        cp_wait0();
        __syncthreads();
    }

    // ---------------- main loop ----------------
    for (int c = 0; c < NCHUNK; c++) {
        const unsigned cur = (unsigned)(c & 1), nxt = cur ^ 1u;

        if (c + 1 < NCHUNK) {
            const float* wsrc = g_wt + (c + 1) * (KC * NEXP);
            #pragma unroll
            for (int j = 0; j < 2; j++) {
                int f = t + j * THREADS;
                cp_async16(sb + SM_W + nxt * W_BYTES + (unsigned)f * 16u, wsrc + f * 4);
            }
            cp_commit();
            #pragma unroll
            for (int j = 0; j < 4; j++) {
                int f = t + j * THREADS;
                int tok = f >> 2, kq = f & 3;
                xv[j] = *(const float4*)(x + (tokBase + tok) * EMBED + (c + 1) * KC + kq * 4);
            }
        }

        // compute chunk c
        {
            const unsigned wb = sb + SM_W + cur * W_BYTES + (unsigned)wid * 64u;
            const unsigned xtb = (unsigned)(SM_XT + cur * XT_BYTES) + (unsigned)lane * 16u;
            #pragma unroll
            for (int k = 0; k < KC; k++) {
                const float4 q0 = *(const float4*)(smx + xtb + (unsigned)k * (TP * 4u));
                u64 a[4];
                a[0] = pack2(q0.x); a[1] = pack2(q0.y);
                a[2] = pack2(q0.z); a[3] = pack2(q0.w);
                u64 b[8];
                lds_v2(b[0], b[1], wb + (unsigned)k * 256u);
                lds_v2(b[2], b[3], wb + (unsigned)k * 256u + 16u);
                lds_v2(b[4], b[5], wb + (unsigned)k * 256u + 32u);
                lds_v2(b[6], b[7], wb + (unsigned)k * 256u + 48u);
                #pragma unroll
                for (int p = 0; p < 8; p++) {
                    #pragma unroll
                    for (int tt = 0; tt < 4; tt++)
                        acc[tt][p] = ffma2(a[tt], b[p], acc[tt][p]);
                }
            }
        }

        if (c + 1 < NCHUNK) {
            float* xt = (float*)(smx + SM_XT + nxt * XT_BYTES);
            #pragma unroll
            for (int j = 0; j < 4; j++) {
                int f = t + j * THREADS;
                int tok = f >> 2, kq = f & 3;
                xt[(kq * 4 + 0) * TP + tok] = xv[j].x;
                xt[(kq * 4 + 1) * TP + tok] = xv[j].y;
                xt[(kq * 4 + 2) * TP + tok] = xv[j].z;
                xt[(kq * 4 + 3) * TP + tok] = xv[j].w;
            }
            cp_wait0();
            __syncthreads();
        }
    }
    __syncthreads();    // GEMM reads done before Ls aliases buffers

    // ---------------- logits -> Ls [128][65] ----------------
    {
        float* L = (float*)(smx + SM_LS);
        #pragma unroll
        for (int tt = 0; tt < 4; tt++) {
            const int row = 4 * lane + tt;
            float* Lr = L + row * 65 + 16 * wid;
            #pragma unroll
            for (int p = 0; p < 8; p++) {
                unsigned lo, hi;
                asm("mov.b64 {%0, %1}, %2;" : "=r"(lo), "=r"(hi) : "l"(acc[tt][p]));
                Lr[2 * p]     = __uint_as_float(lo);
                Lr[2 * p + 1] = __uint_as_float(hi);
            }
        }
    }
    __syncthreads();

    // ---------------- softmax (proven round-4 op order), 1 row/thread ----------------
    {
        float* Lr = (float*)(smx + SM_LS) + t * 65;
        float l[NEXP];
        #pragma unroll
        for (int e = 0; e < NEXP; e++) l[e] = Lr[e];
        float mx = l[0];
        #pragma unroll
        for (int e = 1; e < NEXP; e++) mx = fmaxf(mx, l[e]);
        float ex[NEXP];
        #pragma unroll
        for (int e = 0; e < NEXP; e++) ex[e] = expf(l[e] - mx);
        float v[32];
        #pragma unroll
        for (int j = 0; j < 32; j++) v[j] = ex[j] + ex[j + 32];
        #pragma unroll
        for (int off = 16; off >= 1; off >>= 1) {
            float nv[32];
            #pragma unroll
            for (int j = 0; j < 32; j++) nv[j] = v[j] + v[j ^ off];
            #pragma unroll
            for (int j = 0; j < 32; j++) v[j] = nv[j];
        }
        float s = v[0];
        #pragma unroll
        for (int e = 0; e < NEXP; e++) Lr[e] = ex[e] / s;
    }
    __syncthreads();

    // ---------------- Pi partials (ascending rows; deterministic) ----------------
    if (t < NEXP) {
        const float* L = (const float*)(smx + SM_LS);
        float s1 = 0.f;
        #pragma unroll 4
        for (int r = 0; r < TOKS; r++) s1 += L[r * 65 + t];
        g_pi_part[blockIdx.x][t] = s1;
    }
    __syncthreads();

    // ---------------- top-8 (ascending scan, strict >), 1 row/thread ----------------
    {
        float* Lr = (float*)(smx + SM_LS) + t * 65;
        const long tok = tokBase + t;
        #pragma unroll 1
        for (int kk = 0; kk < TOPK; kk++) {
            float best = -1.f; int bi = 0;
            #pragma unroll
            for (int e = 0; e < NEXP; e++) {
                float vv = Lr[e];
                if (vv > best) { best = vv; bi = e; }
            }
            Lr[bi] = -1.f;
            out[tok * TOPK + kk] = (float)bi;
            out[(long)ntok * TOPK + tok * TOPK + kk] = best;
            atomicAdd((unsigned*)(smx + SM_CNT + 4u * bi), 1u);
        }
    }
    __syncthreads();
    if (t < NEXP) {
        unsigned cv = *(unsigned*)(smx + SM_CNT + 4u * t);
        if (cv) atomicAdd(&g_cnt[t], cv);
    }
}

__global__ void finalize_kernel(float* __restrict__ aux, int nblocks, float ntokf) {
    int e = threadIdx.x;   // 64 threads
    float s = 0.f;
    for (int b = 0; b < nblocks; b++) s += g_pi_part[b][e];
    float Pi = s / ntokf;
    float ce = (float)g_cnt[e] / (ntokf * (float)TOPK);
    float v = Pi * ce * (float)NEXP;
    __shared__ float red[2];
    #pragma unroll
    for (int off = 16; off; off >>= 1)
        v += __shfl_xor_sync(0xffffffffu, v, off);
    if ((e & 31) == 0) red[e >> 5] = v;
    __syncthreads();
    if (e == 0) aux[0] = (red[0] + red[1]) * 0.01f;
}

extern "C" void kernel_launch(void* const* d_in, const int* in_sizes, int n_in,
                              void* d_out, int out_size) {
    const float* x = (const float*)d_in[0];
    const float* w = (const float*)d_in[1];
    float* out = (float*)d_out;
    int ntok = in_sizes[0] / EMBED;        // 32768
    int nblocks = ntok / TOKS;             // 256
    cudaFuncSetAttribute(gate_kernel, cudaFuncAttributeMaxDynamicSharedMemorySize, SMEM_TOTAL);
    prep_kernel<<<(NEXP * EMBED) / 256, 256>>>(w);
    dummy_kernel<<<1, 32>>>();
    dummy_kernel<<<1, 32>>>();
    gate_kernel<<<nblocks, THREADS, SMEM_TOTAL>>>(x, out, ntok);
    finalize_kernel<<<1, 64>>>(out + (long)ntok * 2 * TOPK, nblocks, (float)ntok);
}